// round 13
// baseline (speedup 1.0000x reference)
#include <cuda_runtime.h>

// Problem constants: N=1024, DIM=201, G=200, R=72, C=4
#define NIMG 1024
#define DIMV 201
#define GG   200
#define RR   72
#define CC   4
#define NIT  50     // channel groups: 4 channels each (50*4 = 200)

// Scratch (device globals: allocation-free, graph-safe).
__device__ float        g_loss[NIMG];
__device__ unsigned int g_count = 0;   // reset by last block each run

// One block per image, 96 threads (72 working, one per ROW), 7 blocks/SM
// -> 672 thr/SM -> ~96 regs/thread -> deep per-thread MLP.
// Thread t, channel-group i: loads float4s at i*288 + k*72 + t (k=0..3)
// = channel 4i+k, row t, columns 0..3. All 4 components of one float4 share
// the channel weight 4i+k (compile-time immediate). pos + second differences
// computed fully in registers; no partial-combine smem.
__global__ __launch_bounds__(96, 7) void lane_loss_kernel(
    const float* __restrict__ x, const int* __restrict__ labels,
    float* __restrict__ out)
{
    __shared__ unsigned s_bal[3][CC];   // per-warp validity ballots per column
    __shared__ int      s_top[CC];
    __shared__ int      s_down[CC];
    __shared__ float    s_pl[3], s_pr[3];
    __shared__ bool     s_last;

    const int n    = blockIdx.x;
    const int tid  = threadIdx.x;
    const int wid  = tid >> 5;
    const int lane = tid & 31;

    // ---- label validity: thread t loads its row's 4 labels (int4) ----
    unsigned vm = 0;
    if (tid < RR) {
        int4 lb = ((const int4*)labels)[(size_t)n * RR + tid];
        vm  = (lb.x < GG) ? 1u : 0u;
        vm |= (lb.y < GG) ? 2u : 0u;
        vm |= (lb.z < GG) ? 4u : 0u;
        vm |= (lb.w < GG) ? 8u : 0u;
    }
    #pragma unroll
    for (int c = 0; c < CC; ++c) {
        unsigned b = __ballot_sync(0xffffffffu, (vm >> c) & 1u);
        if (lane == 0) s_bal[wid][c] = b;
    }
    __syncthreads();

    // threads 0..3 parse top/down for column tid (72-bit mask bit logic)
    if (tid < CC) {
        unsigned long long lo = (unsigned long long)s_bal[0][tid]
                              | ((unsigned long long)s_bal[1][tid] << 32);
        unsigned hi = s_bal[2][tid] & 0xFFu;   // rows 64..71

        const bool any = (lo | (unsigned long long)hi) != 0ull;
        int top;
        if (lo)      top = __ffsll((long long)lo) - 1;
        else if (hi) top = 64 + __ffs(hi) - 1;
        else         top = 0;

        // trans[r] = v[r] & !v[r+1], r in [0,70]
        unsigned long long sv  = (lo >> 1) | ((unsigned long long)(hi & 1u) << 63);
        unsigned long long tlo = lo & ~sv;
        unsigned           thi = hi & ~(hi >> 1) & 0x7Fu;
        const bool any_trans = (tlo != 0ull) || (thi != 0u);
        int first_trans;
        if (tlo)      first_trans = __ffsll((long long)tlo) - 1;
        else if (thi) first_trans = 64 + __ffs(thi) - 1;
        else          first_trans = 0;

        const bool v0    = (lo & 1ull) != 0ull;
        const bool v1    = ((lo >> 1) & 1ull) != 0ull;
        const bool vlast = ((hi >> 7) & 1u) != 0u;
        int down = (v0 && !v1) ? 0
                 : (vlast ? (RR - 1)
                 : (any_trans ? first_trans : 0));
        if (!any) { top = 0; down = 0; }
        s_top[tid]  = top;
        s_down[tid] = down;
    }

    // ---- main loop: per-row softmax sums, all in registers ----
    float s0 = 0.f, s1 = 0.f, s2 = 0.f, s3 = 0.f;   // sum(exp) per column
    float p0 = 0.f, p1 = 0.f, p2 = 0.f, p3 = 0.f;   // sum(w*exp) per column
    if (tid < RR) {
        const float4* xp = (const float4*)x + (size_t)n * (DIMV * 72) + tid;
        #pragma unroll
        for (int i = 0; i < NIT; ++i) {
            float4 v0 = xp[i * 288];          // channel 4i
            float4 v1 = xp[i * 288 + 72];     // channel 4i+1
            float4 v2 = xp[i * 288 + 144];    // channel 4i+2
            float4 v3 = xp[i * 288 + 216];    // channel 4i+3
            const float w0 = (float)(4 * i);
            const float w1 = (float)(4 * i + 1);
            const float w2 = (float)(4 * i + 2);
            const float w3 = (float)(4 * i + 3);
            float e;
            e = __expf(v0.x); s0 += e; p0 = fmaf(e, w0, p0);
            e = __expf(v0.y); s1 += e; p1 = fmaf(e, w0, p1);
            e = __expf(v0.z); s2 += e; p2 = fmaf(e, w0, p2);
            e = __expf(v0.w); s3 += e; p3 = fmaf(e, w0, p3);
            e = __expf(v1.x); s0 += e; p0 = fmaf(e, w1, p0);
            e = __expf(v1.y); s1 += e; p1 = fmaf(e, w1, p1);
            e = __expf(v1.z); s2 += e; p2 = fmaf(e, w1, p2);
            e = __expf(v1.w); s3 += e; p3 = fmaf(e, w1, p3);
            e = __expf(v2.x); s0 += e; p0 = fmaf(e, w2, p0);
            e = __expf(v2.y); s1 += e; p1 = fmaf(e, w2, p1);
            e = __expf(v2.z); s2 += e; p2 = fmaf(e, w2, p2);
            e = __expf(v2.w); s3 += e; p3 = fmaf(e, w2, p3);
            e = __expf(v3.x); s0 += e; p0 = fmaf(e, w3, p0);
            e = __expf(v3.y); s1 += e; p1 = fmaf(e, w3, p1);
            e = __expf(v3.z); s2 += e; p2 = fmaf(e, w3, p2);
            e = __expf(v3.w); s3 += e; p3 = fmaf(e, w3, p3);
        }
    }

    // per-row pos + second differences (registers only)
    const float pos0 = __fdividef(p0, s0);
    const float pos1 = __fdividef(p1, s1);
    const float pos2 = __fdividef(p2, s2);
    const float pos3 = __fdividef(p3, s3);
    const float ddl = fabsf(pos0 - 2.0f * pos1 + pos2);
    const float ddr = fabsf(pos1 - 2.0f * pos2 + pos3);

    __syncthreads();   // s_top/s_down visible

    const int tl = max(s_top[0],  max(s_top[1],  s_top[2]));
    const int dl = min(s_down[0], min(s_down[1], s_down[2]));
    const int tr = max(s_top[1],  max(s_top[2],  s_top[3]));
    const int dr = min(s_down[1], min(s_down[2], s_down[3]));

    float cl = (tid < RR && tid >= tl && tid <= dl) ? ddl : 0.0f;
    float cr = (tid < RR && tid >= tr && tid <= dr) ? ddr : 0.0f;
    #pragma unroll
    for (int o = 16; o > 0; o >>= 1) {
        cl += __shfl_down_sync(0xffffffffu, cl, o);
        cr += __shfl_down_sync(0xffffffffu, cr, o);
    }
    if (lane == 0) { s_pl[wid] = cl; s_pr[wid] = cr; }
    __syncthreads();

    if (tid == 0) {
        const bool al = (tl < dl);
        const bool ar = (tr < dr);
        float suml = s_pl[0] + s_pl[1] + s_pl[2];
        float sumr = s_pr[0] + s_pr[1] + s_pr[2];
        float contrib = 0.0f;
        if (al) contrib += suml / (float)(dl - tl + 1);
        if (ar) contrib += sumr / (float)(dr - tr + 1);
        float denom = (al && ar) ? (2.0f * (float)RR) : (float)RR;
        g_loss[n] = contrib / denom;

        __threadfence();
        unsigned int old = atomicAdd(&g_count, 1u);
        s_last = (old == NIMG - 1);
    }
    __syncthreads();

    // ---- last block: deterministic fixed-order global reduction ----
    if (s_last) {
        float sum = 0.0f;
        int   cnt = 0;
        for (int i = tid; i < NIMG; i += 96) {
            float v = g_loss[i];
            sum += v;
            cnt += (v != 0.0f) ? 1 : 0;
        }
        #pragma unroll
        for (int o = 16; o > 0; o >>= 1) {
            sum += __shfl_down_sync(0xffffffffu, sum, o);
            cnt += __shfl_down_sync(0xffffffffu, cnt, o);
        }
        __shared__ float wsum[3];
        __shared__ int   wcnt[3];
        if (lane == 0) { wsum[wid] = sum; wcnt[wid] = cnt; }
        __syncthreads();
        if (tid == 0) {
            float ts = wsum[0] + wsum[1] + wsum[2];
            int   tc = wcnt[0] + wcnt[1] + wcnt[2];
            out[0] = (tc > 0) ? (ts / (float)tc) : 0.0f;
            g_count = 0;   // reset for next graph replay
        }
    }
}

extern "C" void kernel_launch(void* const* d_in, const int* in_sizes, int n_in,
                              void* d_out, int out_size)
{
    const float* x      = (const float*)d_in[0];   // [1024, 201, 72, 4] f32
    const int*   labels = (const int*)d_in[1];     // [1024, 72, 4] int32
    float*       out    = (float*)d_out;           // scalar f32

    lane_loss_kernel<<<NIMG, 96>>>(x, labels, out);
}

// round 14
// speedup vs baseline: 1.0303x; 1.0303x over previous
#include <cuda_runtime.h>

// Problem constants: N=1024, DIM=201, G=200, R=72, C=4
#define NIMG 1024
#define DIMV 201
#define GG   200
#define RR   72
#define CC   4
#define RC   288    // R*C floats per channel (contiguous)
#define NIT  25     // iterations; each covers 4 channels from TWO streams (8 total)
#define HOFF 7200   // 100 channels * 72 float4 = offset of stream B
#define PFD  6      // L2 prefetch distance (iterations ahead)

// Scratch (device globals: allocation-free, graph-safe).
__device__ float        g_loss[NIMG];
__device__ unsigned int g_count = 0;   // reset by last block each run

__device__ __forceinline__ void l2_prefetch(const void* p) {
    asm volatile("prefetch.global.L2 [%0];" :: "l"(p));
}

// One block per image, 288 threads, 7 blocks/SM -> all 1024 blocks in ONE wave.
// Dual-stream (ch 0..99 / 100..199) with register MLP=2, plus register-free
// L2 prefetch PFD iterations ahead (1 lane per 128B line) to deepen the
// effective memory pipeline past the 32-register ceiling.
__global__ __launch_bounds__(RC, 7) void lane_loss_kernel(
    const float* __restrict__ x, const int* __restrict__ labels,
    float* __restrict__ out)
{
    __shared__ float sS[CC][RC];           // partial sum(exp) per residue q
    __shared__ float sP[CC][RC];           // partial sum(w*exp) per residue q
    __shared__ float s_pos[RC];            // row-major: s_pos[r*4+c]
    __shared__ int   s_top[CC];
    __shared__ int   s_down[CC];
    __shared__ bool  s_last;

    const int n   = blockIdx.x;
    const int tid = threadIdx.x;
    const int q   = tid / 72;         // channel residue class 0..3
    const int m   = tid % 72;         // float4 slot group 0..71

    // ---- head: warp 0 loads all labels + parses top/down (no barrier) ----
    if (tid < 32) {
        const int* lp = labels + (size_t)n * RC;
        unsigned bal[9];
        #pragma unroll
        for (int j = 0; j < 9; ++j)
            bal[j] = __ballot_sync(0xffffffffu, lp[j * 32 + tid] < GG);

        if (tid < CC) {
            // 72-bit validity mask for column tid: row 8w+k <- ballot w bit (4k+tid)
            unsigned long long lo = 0ull;   // rows 0..63
            unsigned hi = 0u;               // rows 64..71
            #pragma unroll
            for (int w = 0; w < 8; ++w) {
                #pragma unroll
                for (int k = 0; k < 8; ++k)
                    lo |= (unsigned long long)((bal[w] >> (4 * k + tid)) & 1u)
                          << (8 * w + k);
            }
            #pragma unroll
            for (int k = 0; k < 8; ++k)
                hi |= ((bal[8] >> (4 * k + tid)) & 1u) << k;

            const bool any = (lo | (unsigned long long)hi) != 0ull;
            int top;
            if (lo)      top = __ffsll((long long)lo) - 1;
            else if (hi) top = 64 + __ffs(hi) - 1;
            else         top = 0;

            // trans[r] = v[r] & !v[r+1], r in [0,70]
            unsigned long long sv  = (lo >> 1) | ((unsigned long long)(hi & 1u) << 63);
            unsigned long long tlo = lo & ~sv;
            unsigned           thi = hi & ~(hi >> 1) & 0x7Fu;
            const bool any_trans = (tlo != 0ull) || (thi != 0u);
            int first_trans;
            if (tlo)      first_trans = __ffsll((long long)tlo) - 1;
            else if (thi) first_trans = 64 + __ffs(thi) - 1;
            else          first_trans = 0;

            const bool v0    = (lo & 1ull) != 0ull;
            const bool v1    = ((lo >> 1) & 1ull) != 0ull;
            const bool vlast = ((hi >> 7) & 1u) != 0u;
            int down = (v0 && !v1) ? 0
                     : (vlast ? (RR - 1)
                     : (any_trans ? first_trans : 0));
            if (!any) { top = 0; down = 0; }
            s_top[tid]  = top;
            s_down[tid] = down;
        }
    }

    // ---- Phase 1: dual-stream exp accumulation + L2 prefetch ----
    {
        const float4* xp = (const float4*)x + (size_t)n * (DIMV * 72) + tid;
        const bool pf = ((tid & 7) == 0);   // one lane per 128B line
        float s0 = 0.f, s1 = 0.f, s2 = 0.f, s3 = 0.f;
        float p0 = 0.f, p1 = 0.f, p2 = 0.f, p3 = 0.f;

        // prefetch the first PFD iterations' lines
        if (pf) {
            #pragma unroll
            for (int i = 0; i < PFD; ++i) {
                l2_prefetch(xp + i * 288);
                l2_prefetch(xp + i * 288 + HOFF);
            }
        }

        #pragma unroll
        for (int i = 0; i < NIT; ++i) {
            if (pf && (i + PFD < NIT)) {
                l2_prefetch(xp + (i + PFD) * 288);
                l2_prefetch(xp + (i + PFD) * 288 + HOFF);
            }
            float4 a = xp[i * 288];            // stream A: channels 4i+q
            float4 b = xp[i * 288 + HOFF];     // stream B: channels 100+4i+q
            const float wa = (float)(4 * i);          // FFMA immediates
            const float wb = (float)(4 * i + 100);

            float a0 = __expf(a.x), a1 = __expf(a.y);
            float a2 = __expf(a.z), a3 = __expf(a.w);
            float b0 = __expf(b.x), b1 = __expf(b.y);
            float b2 = __expf(b.z), b3 = __expf(b.w);

            s0 += a0 + b0;  p0 = fmaf(a0, wa, p0);  p0 = fmaf(b0, wb, p0);
            s1 += a1 + b1;  p1 = fmaf(a1, wa, p1);  p1 = fmaf(b1, wb, p1);
            s2 += a2 + b2;  p2 = fmaf(a2, wa, p2);  p2 = fmaf(b2, wb, p2);
            s3 += a3 + b3;  p3 = fmaf(a3, wa, p3);  p3 = fmaf(b3, wb, p3);
        }
        // fold in channel residue: true weight = (4i [+100]) + q
        const float fq = (float)q;
        p0 = fmaf(fq, s0, p0);
        p1 = fmaf(fq, s1, p1);
        p2 = fmaf(fq, s2, p2);
        p3 = fmaf(fq, s3, p3);

        const int base = m * 4;
        sS[q][base + 0] = s0;  sP[q][base + 0] = p0;
        sS[q][base + 1] = s1;  sP[q][base + 1] = p1;
        sS[q][base + 2] = s2;  sP[q][base + 2] = p2;
        sS[q][base + 3] = s3;  sP[q][base + 3] = p3;
    }
    __syncthreads();

    // ---- combine residue partials -> pos ----
    {
        float s = sS[0][tid] + sS[1][tid] + sS[2][tid] + sS[3][tid];
        float p = sP[0][tid] + sP[1][tid] + sP[2][tid] + sP[3][tid];
        s_pos[tid] = __fdividef(p, s);
    }
    __syncthreads();

    // ---- per-image loss: parallel over warp 0 ----
    if (tid < 32) {
        const int tl = max(s_top[0],  max(s_top[1],  s_top[2]));
        const int dl = min(s_down[0], min(s_down[1], s_down[2]));
        const int tr = max(s_top[1],  max(s_top[2],  s_top[3]));
        const int dr = min(s_down[1], min(s_down[2], s_down[3]));
        const bool al = (tl < dl);
        const bool ar = (tr < dr);

        float suml = 0.0f, sumr = 0.0f;
        const float4* pos4 = (const float4*)s_pos;
        #pragma unroll
        for (int k = 0; k < 3; ++k) {
            int r = tid + k * 32;
            if (r < RR) {
                float4 qv = pos4[r];
                float ddl = fabsf(qv.x - 2.0f * qv.y + qv.z);
                float ddr = fabsf(qv.y - 2.0f * qv.z + qv.w);
                if (r >= tl && r <= dl) suml += ddl;
                if (r >= tr && r <= dr) sumr += ddr;
            }
        }
        #pragma unroll
        for (int o = 16; o > 0; o >>= 1) {
            suml += __shfl_down_sync(0xffffffffu, suml, o);
            sumr += __shfl_down_sync(0xffffffffu, sumr, o);
        }
        if (tid == 0) {
            float contrib = 0.0f;
            if (al) contrib += suml / (float)(dl - tl + 1);
            if (ar) contrib += sumr / (float)(dr - tr + 1);
            float denom = (al && ar) ? (2.0f * (float)RR) : (float)RR;
            g_loss[n] = contrib / denom;

            __threadfence();
            unsigned int old = atomicAdd(&g_count, 1u);
            s_last = (old == NIMG - 1);
        }
    }
    __syncthreads();

    // ---- last block: deterministic fixed-order global reduction ----
    if (s_last) {
        float sum = 0.0f;
        int   cnt = 0;
        #pragma unroll
        for (int k = 0; k < 4; ++k) {
            int i = tid + k * RC;            // covers 0..1151
            if (i < NIMG) {
                float v = g_loss[i];
                sum += v;
                cnt += (v != 0.0f) ? 1 : 0;
            }
        }
        #pragma unroll
        for (int o = 16; o > 0; o >>= 1) {
            sum += __shfl_down_sync(0xffffffffu, sum, o);
            cnt += __shfl_down_sync(0xffffffffu, cnt, o);
        }
        __shared__ float wsum[9];
        __shared__ int   wcnt[9];
        const int wid = tid >> 5, lid = tid & 31;
        if (lid == 0) { wsum[wid] = sum; wcnt[wid] = cnt; }
        __syncthreads();
        if (tid == 0) {
            float ts = 0.0f; int tc = 0;
            #pragma unroll
            for (int w = 0; w < 9; ++w) { ts += wsum[w]; tc += wcnt[w]; }
            out[0] = (tc > 0) ? (ts / (float)tc) : 0.0f;
            g_count = 0;   // reset for next graph replay
        }
    }
}

extern "C" void kernel_launch(void* const* d_in, const int* in_sizes, int n_in,
                              void* d_out, int out_size)
{
    const float* x      = (const float*)d_in[0];   // [1024, 201, 72, 4] f32
    const int*   labels = (const int*)d_in[1];     // [1024, 72, 4] int32
    float*       out    = (float*)d_out;           // scalar f32

    lane_loss_kernel<<<NIMG, RC>>>(x, labels, out);
}

// round 15
// speedup vs baseline: 1.1160x; 1.0831x over previous
#include <cuda_runtime.h>

// Problem constants: N=1024, DIM=201, G=200, R=72, C=4
#define NIMG 1024
#define NBLK 2048   // 2 blocks per image (half the rows each)
#define DIMV 201
#define GG   200
#define RR   72
#define CC   4
#define NT   144    // threads per block: k = t/36 (channel residue), j = t%36 (row)
#define NIT  50     // channel groups of 4

// Scratch (device globals: allocation-free, graph-safe; zero-initialized once,
// every nonzero transient is reset by its consumer -> graph-replay safe).
__device__ float        g_sl[NBLK];
__device__ float        g_sr[NBLK];
__device__ float        g_loss[NIMG];
__device__ unsigned int g_icnt[NIMG];   // per-image arrival count (reset by finisher)
__device__ unsigned int g_done = 0;     // images completed (reset by last)

// 2048 blocks x 144 threads, 14 blocks/SM -> 2016 thr/SM, ONE wave.
// Block b: image n=b>>1, row-half h=b&1 (rows [36h, 36h+36)).
// Thread t: channel residue k=t/36, local row j=t%36; loads float4
// (4i+k)*72 + 36h + j over i=0..49 (weight 4i immediate, k folded at end).
__global__ __launch_bounds__(NT, 14) void lane_loss_kernel(
    const float* __restrict__ x, const int* __restrict__ labels,
    float* __restrict__ out)
{
    __shared__ float sS[CC][NT];     // partial sum(exp): [k][j*4+c]
    __shared__ float sP[CC][NT];     // partial sum(w*exp)
    __shared__ float s_cl[36], s_cr[36];
    __shared__ int   s_top[CC], s_down[CC];
    __shared__ float s_red[NT];
    __shared__ int   s_redc[NT];
    __shared__ bool  s_last;

    const int b   = blockIdx.x;
    const int n   = b >> 1;
    const int h   = b & 1;
    const int tid = threadIdx.x;
    const int k   = tid / 36;
    const int j   = tid % 36;

    if (tid == 0) s_last = false;

    // ---- warp 0: load ALL 288 labels of image n, parse top/down ----
    if (tid < 32) {
        const int* lp = labels + (size_t)n * (RR * CC);
        unsigned bal[9];
        #pragma unroll
        for (int w = 0; w < 9; ++w)
            bal[w] = __ballot_sync(0xffffffffu, lp[w * 32 + tid] < GG);

        if (tid < CC) {
            unsigned long long lo = 0ull;   // rows 0..63, column tid
            unsigned hi = 0u;               // rows 64..71
            #pragma unroll
            for (int w = 0; w < 8; ++w) {
                #pragma unroll
                for (int kk = 0; kk < 8; ++kk)
                    lo |= (unsigned long long)((bal[w] >> (4 * kk + tid)) & 1u)
                          << (8 * w + kk);
            }
            #pragma unroll
            for (int kk = 0; kk < 8; ++kk)
                hi |= ((bal[8] >> (4 * kk + tid)) & 1u) << kk;

            const bool any = (lo | (unsigned long long)hi) != 0ull;
            int top;
            if (lo)      top = __ffsll((long long)lo) - 1;
            else if (hi) top = 64 + __ffs(hi) - 1;
            else         top = 0;

            unsigned long long sv  = (lo >> 1) | ((unsigned long long)(hi & 1u) << 63);
            unsigned long long tlo = lo & ~sv;
            unsigned           thi = hi & ~(hi >> 1) & 0x7Fu;
            const bool any_trans = (tlo != 0ull) || (thi != 0u);
            int ft;
            if (tlo)      ft = __ffsll((long long)tlo) - 1;
            else if (thi) ft = 64 + __ffs(thi) - 1;
            else          ft = 0;

            const bool v0    = (lo & 1ull) != 0ull;
            const bool v1    = ((lo >> 1) & 1ull) != 0ull;
            const bool vlast = ((hi >> 7) & 1u) != 0u;
            int down = (v0 && !v1) ? 0
                     : (vlast ? (RR - 1)
                     : (any_trans ? ft : 0));
            if (!any) { top = 0; down = 0; }
            s_top[tid]  = top;
            s_down[tid] = down;
        }
    }

    // ---- main loop: 50 LDG.128, single base + immediate offsets ----
    {
        const float4* xp = (const float4*)x + (size_t)n * (DIMV * 72)
                           + k * 72 + h * 36 + j;
        float s0 = 0.f, s1 = 0.f, s2 = 0.f, s3 = 0.f;
        float p0 = 0.f, p1 = 0.f, p2 = 0.f, p3 = 0.f;
        #pragma unroll
        for (int i = 0; i < NIT; ++i) {
            float4 v = xp[i * 288];            // channel 4i+k, row 36h+j, cols 0..3
            const float w = (float)(4 * i);    // FFMA immediate
            float e0 = __expf(v.x), e1 = __expf(v.y);
            float e2 = __expf(v.z), e3 = __expf(v.w);
            s0 += e0; p0 = fmaf(e0, w, p0);
            s1 += e1; p1 = fmaf(e1, w, p1);
            s2 += e2; p2 = fmaf(e2, w, p2);
            s3 += e3; p3 = fmaf(e3, w, p3);
        }
        const float fk = (float)k;             // fold residue: weight = 4i + k
        p0 = fmaf(fk, s0, p0);
        p1 = fmaf(fk, s1, p1);
        p2 = fmaf(fk, s2, p2);
        p3 = fmaf(fk, s3, p3);

        const int base = j * 4;
        sS[k][base + 0] = s0;  sP[k][base + 0] = p0;
        sS[k][base + 1] = s1;  sP[k][base + 1] = p1;
        sS[k][base + 2] = s2;  sP[k][base + 2] = p2;
        sS[k][base + 3] = s3;  sP[k][base + 3] = p3;
    }
    __syncthreads();

    // ---- threads 0..35: combine residues, pos, dd, mask by [t,d] ----
    if (tid < 36) {
        const int r  = h * 36 + tid;           // global row
        const int i0 = tid * 4;
        float pos[4];
        #pragma unroll
        for (int c = 0; c < 4; ++c) {
            float s = sS[0][i0 + c] + sS[1][i0 + c] + sS[2][i0 + c] + sS[3][i0 + c];
            float p = sP[0][i0 + c] + sP[1][i0 + c] + sP[2][i0 + c] + sP[3][i0 + c];
            pos[c] = __fdividef(p, s);
        }
        const float ddl = fabsf(pos[0] - 2.0f * pos[1] + pos[2]);
        const float ddr = fabsf(pos[1] - 2.0f * pos[2] + pos[3]);

        const int tl = max(s_top[0],  max(s_top[1],  s_top[2]));
        const int dl = min(s_down[0], min(s_down[1], s_down[2]));
        const int tr = max(s_top[1],  max(s_top[2],  s_top[3]));
        const int dr = min(s_down[1], min(s_down[2], s_down[3]));
        s_cl[tid] = (r >= tl && r <= dl) ? ddl : 0.0f;
        s_cr[tid] = (r >= tr && r <= dr) ? ddr : 0.0f;
    }
    __syncthreads();

    // ---- thread 0: publish partials; 2nd finisher composes image loss ----
    if (tid == 0) {
        float psl = 0.0f, psr = 0.0f;
        #pragma unroll
        for (int i = 0; i < 36; ++i) { psl += s_cl[i]; psr += s_cr[i]; }
        g_sl[b] = psl;
        g_sr[b] = psr;
        __threadfence();
        unsigned old = atomicAdd(&g_icnt[n], 1u);
        if (old == 1u) {                       // both halves done
            volatile float* vsl = g_sl;
            volatile float* vsr = g_sr;
            const float suml = vsl[2 * n] + vsl[2 * n + 1];   // fixed order
            const float sumr = vsr[2 * n] + vsr[2 * n + 1];
            const int tl = max(s_top[0],  max(s_top[1],  s_top[2]));
            const int dl = min(s_down[0], min(s_down[1], s_down[2]));
            const int tr = max(s_top[1],  max(s_top[2],  s_top[3]));
            const int dr = min(s_down[1], min(s_down[2], s_down[3]));
            const bool al = (tl < dl);
            const bool ar = (tr < dr);
            float contrib = 0.0f;
            if (al) contrib += suml / (float)(dl - tl + 1);
            if (ar) contrib += sumr / (float)(dr - tr + 1);
            const float denom = (al && ar) ? (2.0f * (float)RR) : (float)RR;
            g_loss[n] = contrib / denom;
            g_icnt[n] = 0u;                    // reset for next replay
            __threadfence();
            unsigned old2 = atomicAdd(&g_done, 1u);
            if (old2 == NIMG - 1) {
                s_last = true;
                g_done = 0u;                   // reset for next replay
            }
        }
    }
    __syncthreads();

    // ---- last block: deterministic fixed-order reduction of g_loss ----
    if (s_last) {
        volatile float* vl = g_loss;
        float sum = 0.0f;
        int   cnt = 0;
        for (int i = tid; i < NIMG; i += NT) { // fixed stride order per thread
            float v = vl[i];
            sum += v;
            cnt += (v != 0.0f) ? 1 : 0;
        }
        s_red[tid]  = sum;
        s_redc[tid] = cnt;
        __syncthreads();
        if (tid < 16) {
            float ts = 0.0f; int tc = 0;
            #pragma unroll
            for (int w = 0; w < 9; ++w) { ts += s_red[tid + w * 16]; tc += s_redc[tid + w * 16]; }
            s_red[tid] = ts; s_redc[tid] = tc;
        }
        __syncthreads();
        if (tid == 0) {
            float ts = 0.0f; int tc = 0;
            #pragma unroll
            for (int w = 0; w < 16; ++w) { ts += s_red[w]; tc += s_redc[w]; }
            out[0] = (tc > 0) ? (ts / (float)tc) : 0.0f;
        }
    }
}

extern "C" void kernel_launch(void* const* d_in, const int* in_sizes, int n_in,
                              void* d_out, int out_size)
{
    const float* x      = (const float*)d_in[0];   // [1024, 201, 72, 4] f32
    const int*   labels = (const int*)d_in[1];     // [1024, 72, 4] int32
    float*       out    = (float*)d_out;           // scalar f32

    lane_loss_kernel<<<NBLK, NT>>>(x, labels, out);
}

// round 16
// speedup vs baseline: 1.3272x; 1.1893x over previous
#include <cuda_runtime.h>

// Problem constants: N=1024, DIM=201, G=200, R=72, C=4
#define NIMG 1024
#define DIMV 201
#define GG   200
#define RR   72
#define CC   4
#define RC   288    // R*C floats per channel (contiguous)
#define NIT  17     // iterations; streams A,B run 17 groups, C runs 16
#define OFFB 4896   // 68 channels * 72 float4
#define OFFC 9792   // 136 channels * 72 float4

// Scratch (device globals: allocation-free, graph-safe).
__device__ float        g_loss[NIMG];
__device__ unsigned int g_count = 0;   // reset by last block each run

// One block per image, 288 threads, 7 blocks/SM -> all 1024 blocks in ONE wave.
// THREE independent channel streams per thread (A: ch 0..67, B: 68..135,
// C: 136..199) -> 3 LDG.128 structurally in flight within the 32-reg cap.
// Thread t: float4 index i*288+t (+stream offset) -> channel 4i+t/72 (+68/+136),
// slots 4(t%72)..+3. Warp 0 parses labels via ballots in the head (no barrier).
__global__ __launch_bounds__(RC, 7) void lane_loss_kernel(
    const float* __restrict__ x, const int* __restrict__ labels,
    float* __restrict__ out)
{
    __shared__ float sS[CC][RC];           // partial sum(exp) per residue q
    __shared__ float sP[CC][RC];           // partial sum(w*exp) per residue q
    __shared__ float s_pos[RC];            // row-major: s_pos[r*4+c]
    __shared__ int   s_top[CC];
    __shared__ int   s_down[CC];
    __shared__ bool  s_last;

    const int n   = blockIdx.x;
    const int tid = threadIdx.x;
    const int q   = tid / 72;         // channel residue class 0..3
    const int m   = tid % 72;         // float4 slot group 0..71

    // ---- head: warp 0 loads all labels + parses top/down (no barrier) ----
    if (tid < 32) {
        const int* lp = labels + (size_t)n * RC;
        unsigned bal[9];
        #pragma unroll
        for (int j = 0; j < 9; ++j)
            bal[j] = __ballot_sync(0xffffffffu, lp[j * 32 + tid] < GG);

        if (tid < CC) {
            // 72-bit validity mask for column tid: row 8w+k <- ballot w bit (4k+tid)
            unsigned long long lo = 0ull;   // rows 0..63
            unsigned hi = 0u;               // rows 64..71
            #pragma unroll
            for (int w = 0; w < 8; ++w) {
                #pragma unroll
                for (int k = 0; k < 8; ++k)
                    lo |= (unsigned long long)((bal[w] >> (4 * k + tid)) & 1u)
                          << (8 * w + k);
            }
            #pragma unroll
            for (int k = 0; k < 8; ++k)
                hi |= ((bal[8] >> (4 * k + tid)) & 1u) << k;

            const bool any = (lo | (unsigned long long)hi) != 0ull;
            int top;
            if (lo)      top = __ffsll((long long)lo) - 1;
            else if (hi) top = 64 + __ffs(hi) - 1;
            else         top = 0;

            // trans[r] = v[r] & !v[r+1], r in [0,70]
            unsigned long long sv  = (lo >> 1) | ((unsigned long long)(hi & 1u) << 63);
            unsigned long long tlo = lo & ~sv;
            unsigned           thi = hi & ~(hi >> 1) & 0x7Fu;
            const bool any_trans = (tlo != 0ull) || (thi != 0u);
            int first_trans;
            if (tlo)      first_trans = __ffsll((long long)tlo) - 1;
            else if (thi) first_trans = 64 + __ffs(thi) - 1;
            else          first_trans = 0;

            const bool v0    = (lo & 1ull) != 0ull;
            const bool v1    = ((lo >> 1) & 1ull) != 0ull;
            const bool vlast = ((hi >> 7) & 1u) != 0u;
            int down = (v0 && !v1) ? 0
                     : (vlast ? (RR - 1)
                     : (any_trans ? first_trans : 0));
            if (!any) { top = 0; down = 0; }
            s_top[tid]  = top;
            s_down[tid] = down;
        }
    }

    // ---- Phase 1: triple-stream exp accumulation (MLP=3 structurally) ----
    {
        const float4* xp = (const float4*)x + (size_t)n * (DIMV * 72) + tid;
        float s0 = 0.f, s1 = 0.f, s2 = 0.f, s3 = 0.f;
        float p0 = 0.f, p1 = 0.f, p2 = 0.f, p3 = 0.f;

        #pragma unroll
        for (int i = 0; i < NIT; ++i) {
            float4 a = xp[i * 288];            // stream A: channels 4i+q
            float4 b = xp[i * 288 + OFFB];     // stream B: channels 68+4i+q
            const float wa = (float)(4 * i);          // FFMA immediates
            const float wb = (float)(4 * i + 68);

            if (i < 16) {
                float4 c = xp[i * 288 + OFFC]; // stream C: channels 136+4i+q
                const float wc = (float)(4 * i + 136);

                float a0 = __expf(a.x), a1 = __expf(a.y);
                float a2 = __expf(a.z), a3 = __expf(a.w);
                float b0 = __expf(b.x), b1 = __expf(b.y);
                float b2 = __expf(b.z), b3 = __expf(b.w);
                float c0 = __expf(c.x), c1 = __expf(c.y);
                float c2 = __expf(c.z), c3 = __expf(c.w);

                s0 += a0 + b0 + c0;
                s1 += a1 + b1 + c1;
                s2 += a2 + b2 + c2;
                s3 += a3 + b3 + c3;
                p0 = fmaf(a0, wa, p0); p0 = fmaf(b0, wb, p0); p0 = fmaf(c0, wc, p0);
                p1 = fmaf(a1, wa, p1); p1 = fmaf(b1, wb, p1); p1 = fmaf(c1, wc, p1);
                p2 = fmaf(a2, wa, p2); p2 = fmaf(b2, wb, p2); p2 = fmaf(c2, wc, p2);
                p3 = fmaf(a3, wa, p3); p3 = fmaf(b3, wb, p3); p3 = fmaf(c3, wc, p3);
            } else {
                float a0 = __expf(a.x), a1 = __expf(a.y);
                float a2 = __expf(a.z), a3 = __expf(a.w);
                float b0 = __expf(b.x), b1 = __expf(b.y);
                float b2 = __expf(b.z), b3 = __expf(b.w);

                s0 += a0 + b0;
                s1 += a1 + b1;
                s2 += a2 + b2;
                s3 += a3 + b3;
                p0 = fmaf(a0, wa, p0); p0 = fmaf(b0, wb, p0);
                p1 = fmaf(a1, wa, p1); p1 = fmaf(b1, wb, p1);
                p2 = fmaf(a2, wa, p2); p2 = fmaf(b2, wb, p2);
                p3 = fmaf(a3, wa, p3); p3 = fmaf(b3, wb, p3);
            }
        }
        // fold in channel residue: true weight = (4i [+68/+136]) + q
        const float fq = (float)q;
        p0 = fmaf(fq, s0, p0);
        p1 = fmaf(fq, s1, p1);
        p2 = fmaf(fq, s2, p2);
        p3 = fmaf(fq, s3, p3);

        const int base = m * 4;
        sS[q][base + 0] = s0;  sP[q][base + 0] = p0;
        sS[q][base + 1] = s1;  sP[q][base + 1] = p1;
        sS[q][base + 2] = s2;  sP[q][base + 2] = p2;
        sS[q][base + 3] = s3;  sP[q][base + 3] = p3;
    }
    __syncthreads();

    // ---- combine residue partials -> pos ----
    {
        float s = sS[0][tid] + sS[1][tid] + sS[2][tid] + sS[3][tid];
        float p = sP[0][tid] + sP[1][tid] + sP[2][tid] + sP[3][tid];
        s_pos[tid] = __fdividef(p, s);
    }
    __syncthreads();

    // ---- per-image loss: parallel over warp 0 ----
    if (tid < 32) {
        const int tl = max(s_top[0],  max(s_top[1],  s_top[2]));
        const int dl = min(s_down[0], min(s_down[1], s_down[2]));
        const int tr = max(s_top[1],  max(s_top[2],  s_top[3]));
        const int dr = min(s_down[1], min(s_down[2], s_down[3]));
        const bool al = (tl < dl);
        const bool ar = (tr < dr);

        float suml = 0.0f, sumr = 0.0f;
        const float4* pos4 = (const float4*)s_pos;
        #pragma unroll
        for (int k = 0; k < 3; ++k) {
            int r = tid + k * 32;
            if (r < RR) {
                float4 qv = pos4[r];
                float ddl = fabsf(qv.x - 2.0f * qv.y + qv.z);
                float ddr = fabsf(qv.y - 2.0f * qv.z + qv.w);
                if (r >= tl && r <= dl) suml += ddl;
                if (r >= tr && r <= dr) sumr += ddr;
            }
        }
        #pragma unroll
        for (int o = 16; o > 0; o >>= 1) {
            suml += __shfl_down_sync(0xffffffffu, suml, o);
            sumr += __shfl_down_sync(0xffffffffu, sumr, o);
        }
        if (tid == 0) {
            float contrib = 0.0f;
            if (al) contrib += suml / (float)(dl - tl + 1);
            if (ar) contrib += sumr / (float)(dr - tr + 1);
            float denom = (al && ar) ? (2.0f * (float)RR) : (float)RR;
            g_loss[n] = contrib / denom;

            __threadfence();
            unsigned int old = atomicAdd(&g_count, 1u);
            s_last = (old == NIMG - 1);
        }
    }
    __syncthreads();

    // ---- last block: deterministic fixed-order global reduction ----
    if (s_last) {
        float sum = 0.0f;
        int   cnt = 0;
        #pragma unroll
        for (int k = 0; k < 4; ++k) {
            int i = tid + k * RC;            // covers 0..1151
            if (i < NIMG) {
                float v = g_loss[i];
                sum += v;
                cnt += (v != 0.0f) ? 1 : 0;
            }
        }
        #pragma unroll
        for (int o = 16; o > 0; o >>= 1) {
            sum += __shfl_down_sync(0xffffffffu, sum, o);
            cnt += __shfl_down_sync(0xffffffffu, cnt, o);
        }
        __shared__ float wsum[9];
        __shared__ int   wcnt[9];
        const int wid = tid >> 5, lid = tid & 31;
        if (lid == 0) { wsum[wid] = sum; wcnt[wid] = cnt; }
        __syncthreads();
        if (tid == 0) {
            float ts = 0.0f; int tc = 0;
            #pragma unroll
            for (int w = 0; w < 9; ++w) { ts += wsum[w]; tc += wcnt[w]; }
            out[0] = (tc > 0) ? (ts / (float)tc) : 0.0f;
            g_count = 0;   // reset for next graph replay
        }
    }
}

extern "C" void kernel_launch(void* const* d_in, const int* in_sizes, int n_in,
                              void* d_out, int out_size)
{
    const float* x      = (const float*)d_in[0];   // [1024, 201, 72, 4] f32
    const int*   labels = (const int*)d_in[1];     // [1024, 72, 4] int32
    float*       out    = (float*)d_out;           // scalar f32

    lane_loss_kernel<<<NIMG, RC>>>(x, labels, out);
}